// round 3
// baseline (speedup 1.0000x reference)
#include <cuda_runtime.h>
#include <cuda_bf16.h>

// x = (N=2, C=16, D=96, H=128, W=128) fp32; out = concat(gx, gy, gz).

#define W_   128
#define H_   128
#define D_   96
#define NC_  32
#define YT_  8      // y rows per tile (one warp per row)
#define ZC_  24     // z outputs per tile
#define TILES_Y 16  // H/YT
#define TILES_Z 4   // D/ZC
#define NTILES (TILES_Y * TILES_Z * NC_)   // 2048
#define GRID_ 444   // 148 SMs * 3 resident CTAs

__device__ __forceinline__ float4 ld4z(const float* p, bool ok) {
    if (ok) return *reinterpret_cast<const float4*>(p);
    return make_float4(0.f, 0.f, 0.f, 0.f);
}

__global__ __launch_bounds__(256, 3)
void sobel3d_kernel(const float* __restrict__ in, float* __restrict__ out) {
    const int lane = threadIdx.x;       // 0..31
    const int x4   = lane * 4;

    const long long HW = (long long)H_ * W_;
    const long long V  = (long long)NC_ * D_ * HW;
    float* gx = out;
    float* gy = out + V;
    float* gz = out + 2 * V;

    for (int t = blockIdx.x; t < NTILES; t += GRID_) {
        const int yt = t & (TILES_Y - 1);
        const int zt = (t >> 4) & (TILES_Z - 1);
        const int nc = t >> 6;

        const int y  = yt * YT_ + threadIdx.y;
        const int z0 = zt * ZC_;

        const float* src = in + (long long)nc * D_ * HW;
        const bool ym_ok = (y > 0);
        const bool yp_ok = (y < H_ - 1);
        const int roff_m = (y - 1) * W_ + x4;
        const int roff_0 = y * W_ + x4;
        const int roff_p = (y + 1) * W_ + x4;
        const long long obase = (long long)nc * D_ * HW + (long long)y * W_ + x4;

        // z register rings for the three per-plane partials
        float4 zero = make_float4(0.f, 0.f, 0.f, 0.f);
        float4 am = zero, a0 = zero;
        float4 bm = zero, b0 = zero;
        float4 cm = zero, c0 = zero;

        // prefetch plane pz = z0-1
        float4 f_m, f_0, f_p;
        {
            const int pz = z0 - 1;
            const bool zin = (pz >= 0);
            const float* pl = src + (long long)pz * HW;
            f_m = ld4z(pl + roff_m, zin && ym_ok);
            f_0 = ld4z(pl + roff_0, zin);
            f_p = ld4z(pl + roff_p, zin && yp_ok);
        }

        #pragma unroll 2
        for (int i = 0; i < ZC_ + 2; ++i) {
            const int pz = z0 - 1 + i;

            // consume prefetched plane
            float4 rm = f_m, r0 = f_0, rp = f_p;

            // issue next plane's loads before compute/stores (latency hiding)
            if (i < ZC_ + 1) {
                const int nz = pz + 1;
                const bool zin = (nz < D_);
                const float* pl = src + (long long)nz * HW;
                f_m = ld4z(pl + roff_m, zin && ym_ok);
                f_0 = ld4z(pl + roff_0, zin);
                f_p = ld4z(pl + roff_p, zin && yp_ok);
            }

            // vertical (y) combos
            float4 d, s;
            d.x = rp.x - rm.x; d.y = rp.y - rm.y; d.z = rp.z - rm.z; d.w = rp.w - rm.w;
            s.x = rm.x + 2.f*r0.x + rp.x;
            s.y = rm.y + 2.f*r0.y + rp.y;
            s.z = rm.z + 2.f*r0.z + rp.z;
            s.w = rm.w + 2.f*r0.w + rp.w;

            // horizontal halo via warp shuffles (row == one warp)
            float sL = __shfl_up_sync(0xffffffffu, s.w, 1);
            float sR = __shfl_down_sync(0xffffffffu, s.x, 1);
            float dL = __shfl_up_sync(0xffffffffu, d.w, 1);
            float dR = __shfl_down_sync(0xffffffffu, d.x, 1);
            if (lane == 0)  { sL = 0.f; dL = 0.f; }
            if (lane == 31) { sR = 0.f; dR = 0.f; }

            float4 ap, bp, cp;
            ap.x = s.y - sL;  ap.y = s.z - s.x;  ap.z = s.w - s.y;  ap.w = sR - s.z;
            bp.x = dL + 2.f*d.x + d.y;
            bp.y = d.x + 2.f*d.y + d.z;
            bp.z = d.y + 2.f*d.z + d.w;
            bp.w = d.z + 2.f*d.w + dR;
            cp.x = sL + 2.f*s.x + s.y;
            cp.y = s.x + 2.f*s.y + s.z;
            cp.z = s.y + 2.f*s.z + s.w;
            cp.w = s.z + 2.f*s.w + sR;

            if (i >= 2) {
                const int oz = pz - 1;
                const long long o = obase + (long long)oz * HW;
                float4 vx, vy, vz;
                vx.x = am.x + 2.f*a0.x + ap.x;
                vx.y = am.y + 2.f*a0.y + ap.y;
                vx.z = am.z + 2.f*a0.z + ap.z;
                vx.w = am.w + 2.f*a0.w + ap.w;
                vy.x = bm.x + 2.f*b0.x + bp.x;
                vy.y = bm.y + 2.f*b0.y + bp.y;
                vy.z = bm.z + 2.f*b0.z + bp.z;
                vy.w = bm.w + 2.f*b0.w + bp.w;
                vz.x = cp.x - cm.x; vz.y = cp.y - cm.y;
                vz.z = cp.z - cm.z; vz.w = cp.w - cm.w;
                *reinterpret_cast<float4*>(gx + o) = vx;
                *reinterpret_cast<float4*>(gy + o) = vy;
                *reinterpret_cast<float4*>(gz + o) = vz;
            }
            am = a0; a0 = ap;
            bm = b0; b0 = bp;
            cm = c0; c0 = cp;
        }
    }
}

extern "C" void kernel_launch(void* const* d_in, const int* in_sizes, int n_in,
                              void* d_out, int out_size) {
    const float* x = (const float*)d_in[0];
    float* out = (float*)d_out;

    dim3 block(32, YT_, 1);        // 256 threads
    dim3 grid(GRID_, 1, 1);        // persistent: 148 SMs x 3 CTAs
    sobel3d_kernel<<<grid, block>>>(x, out);
}

// round 4
// speedup vs baseline: 1.0960x; 1.0960x over previous
#include <cuda_runtime.h>
#include <cuda_bf16.h>

// x = (N=2, C=16, D=96, H=128, W=128) fp32; out = concat(gx, gy, gz).

#define W_   128
#define H_   128
#define D_   96
#define NC_  32
#define YT_  8     // rows (warps) per block

__device__ __forceinline__ float4 ld4z(const float* p, bool ok) {
    if (ok) return *reinterpret_cast<const float4*>(p);
    return make_float4(0.f, 0.f, 0.f, 0.f);
}

__global__ __launch_bounds__(256, 4)
void sobel3d_kernel(const float* __restrict__ in, float* __restrict__ out) {
    const int lane = threadIdx.x;             // 0..31
    const int y    = blockIdx.x * YT_ + threadIdx.y;
    const int nc   = blockIdx.y;
    const int x4   = lane * 4;

    const long long HW = (long long)H_ * W_;
    const float* src = in + (long long)nc * D_ * HW;
    const long long V = (long long)NC_ * D_ * HW;
    float* gx = out;
    float* gy = out + V;
    float* gz = out + 2 * V;

    const bool ym_ok = (y > 0);
    const bool yp_ok = (y < H_ - 1);
    const int roff_m = (y - 1) * W_ + x4;
    const int roff_0 = y * W_ + x4;
    const int roff_p = (y + 1) * W_ + x4;
    const long long obase = (long long)nc * D_ * HW + (long long)y * W_ + x4;

    // z register rings for the three per-plane partials
    float4 zero = make_float4(0.f, 0.f, 0.f, 0.f);
    float4 am = zero, a0 = zero;
    float4 bm = zero, b0 = zero;
    float4 cm = zero, c0 = zero;

    #pragma unroll 2
    for (int pz = 0; pz <= D_; ++pz) {
        const bool zin = (pz < D_);
        const float* plane = src + (long long)pz * HW;

        float4 rm = ld4z(plane + roff_m, zin && ym_ok);
        float4 r0 = ld4z(plane + roff_0, zin);
        float4 rp = ld4z(plane + roff_p, zin && yp_ok);

        // vertical (y) combos
        float4 d, s;
        d.x = rp.x - rm.x; d.y = rp.y - rm.y; d.z = rp.z - rm.z; d.w = rp.w - rm.w;
        s.x = rm.x + 2.f*r0.x + rp.x;
        s.y = rm.y + 2.f*r0.y + rp.y;
        s.z = rm.z + 2.f*r0.z + rp.z;
        s.w = rm.w + 2.f*r0.w + rp.w;

        // horizontal halo via shuffles (row is exactly one warp wide)
        float sL = __shfl_up_sync(0xffffffffu, s.w, 1);
        float sR = __shfl_down_sync(0xffffffffu, s.x, 1);
        float dL = __shfl_up_sync(0xffffffffu, d.w, 1);
        float dR = __shfl_down_sync(0xffffffffu, d.x, 1);
        if (lane == 0)  { sL = 0.f; dL = 0.f; }
        if (lane == 31) { sR = 0.f; dR = 0.f; }

        // per-plane partials
        float4 ap, bp, cp;
        ap.x = s.y - sL;  ap.y = s.z - s.x;  ap.z = s.w - s.y;  ap.w = sR - s.z;
        bp.x = dL + 2.f*d.x + d.y;
        bp.y = d.x + 2.f*d.y + d.z;
        bp.z = d.y + 2.f*d.z + d.w;
        bp.w = d.z + 2.f*d.w + dR;
        cp.x = sL + 2.f*s.x + s.y;
        cp.y = s.x + 2.f*s.y + s.z;
        cp.z = s.y + 2.f*s.z + s.w;
        cp.w = s.z + 2.f*s.w + sR;

        if (pz >= 1) {
            const int oz = pz - 1;
            const long long o = obase + (long long)oz * HW;
            float4 vx, vy, vz;
            vx.x = am.x + 2.f*a0.x + ap.x;
            vx.y = am.y + 2.f*a0.y + ap.y;
            vx.z = am.z + 2.f*a0.z + ap.z;
            vx.w = am.w + 2.f*a0.w + ap.w;
            vy.x = bm.x + 2.f*b0.x + bp.x;
            vy.y = bm.y + 2.f*b0.y + bp.y;
            vy.z = bm.z + 2.f*b0.z + bp.z;
            vy.w = bm.w + 2.f*b0.w + bp.w;
            vz.x = cp.x - cm.x; vz.y = cp.y - cm.y;
            vz.z = cp.z - cm.z; vz.w = cp.w - cm.w;
            __stcs(reinterpret_cast<float4*>(gx + o), vx);
            __stcs(reinterpret_cast<float4*>(gy + o), vy);
            __stcs(reinterpret_cast<float4*>(gz + o), vz);
        }
        am = a0; a0 = ap;
        bm = b0; b0 = bp;
        cm = c0; c0 = cp;
    }
}

extern "C" void kernel_launch(void* const* d_in, const int* in_sizes, int n_in,
                              void* d_out, int out_size) {
    const float* x = (const float*)d_in[0];
    float* out = (float*)d_out;

    dim3 block(32, YT_, 1);            // 256 threads
    dim3 grid(H_ / YT_, NC_, 1);       // 16 x 32 = 512 blocks, one wave
    sobel3d_kernel<<<grid, block>>>(x, out);
}

// round 5
// speedup vs baseline: 1.1300x; 1.0310x over previous
#include <cuda_runtime.h>
#include <cuda_bf16.h>

// x = (N=2, C=16, D=96, H=128, W=128) fp32; out = concat(gx, gy, gz).

#define W_   128
#define H_   128
#define D_   96
#define NC_  32
#define YT_  8
#define HW_  (H_ * W_)          // 16384
#define CST_ (D_ * HW_)         // 1572864 (per-nc stride)
#define V_   (NC_ * CST_)       // 50331648 (per-output-tensor elements)

__device__ __forceinline__ float4 ld4z(const float* p, bool ok) {
    if (ok) return *reinterpret_cast<const float4*>(p);
    return make_float4(0.f, 0.f, 0.f, 0.f);
}

__global__ __launch_bounds__(256, 4)
void sobel3d_kernel(const float* __restrict__ in, float* __restrict__ out) {
    const int lane = threadIdx.x;                    // 0..31
    const int y    = blockIdx.x * YT_ + threadIdx.y; // 0..127
    const int nc   = blockIdx.y;                     // 0..31
    const int x4   = lane * 4;

    const float* src = in + nc * CST_;
    float* gx = out;
    float* gy = out + V_;
    float* gz = out + 2 * V_;

    const bool ym_ok = (y > 0);
    const bool yp_ok = (y < H_ - 1);
    const int rm_off = (y - 1) * W_ + x4;
    const int r0_off = y * W_ + x4;
    const int rp_off = (y + 1) * W_ + x4;
    const int obase  = nc * CST_ + y * W_ + x4;

    // z rings of per-plane y-convolutions: s = smooth_y, d = deriv_y
    float4 zz = make_float4(0.f, 0.f, 0.f, 0.f);
    float4 s_m = zz, s_0 = zz, d_m = zz, d_0 = zz;

    // prefetch plane 0
    float4 f_m = ld4z(src + rm_off, ym_ok);
    float4 f_0 = *reinterpret_cast<const float4*>(src + r0_off);
    float4 f_p = ld4z(src + rp_off, yp_ok);

    #pragma unroll 2
    for (int pz = 0; pz <= D_; ++pz) {
        // consume prefetched plane into s/d (frees f_* immediately)
        float4 s_p, d_p;
        d_p.x = f_p.x - f_m.x; d_p.y = f_p.y - f_m.y;
        d_p.z = f_p.z - f_m.z; d_p.w = f_p.w - f_m.w;
        s_p.x = f_m.x + 2.f * f_0.x + f_p.x;
        s_p.y = f_m.y + 2.f * f_0.y + f_p.y;
        s_p.z = f_m.z + 2.f * f_0.z + f_p.z;
        s_p.w = f_m.w + 2.f * f_0.w + f_p.w;

        // issue next plane's loads before the shuffle/store chain
        if (pz < D_) {
            const bool zin = (pz + 1) < D_;
            const float* pl = src + (pz + 1) * HW_;
            f_m = ld4z(pl + rm_off, zin && ym_ok);
            f_0 = ld4z(pl + r0_off, zin);
            f_p = ld4z(pl + rp_off, zin && yp_ok);
        }

        if (pz >= 1) {
            // z-combine first, then x-convolve the combined values
            float4 Sz, Dz, Zz;   // smooth_z(s), smooth_z(d), deriv_z(s)
            Sz.x = s_m.x + 2.f * s_0.x + s_p.x;
            Sz.y = s_m.y + 2.f * s_0.y + s_p.y;
            Sz.z = s_m.z + 2.f * s_0.z + s_p.z;
            Sz.w = s_m.w + 2.f * s_0.w + s_p.w;
            Dz.x = d_m.x + 2.f * d_0.x + d_p.x;
            Dz.y = d_m.y + 2.f * d_0.y + d_p.y;
            Dz.z = d_m.z + 2.f * d_0.z + d_p.z;
            Dz.w = d_m.w + 2.f * d_0.w + d_p.w;
            Zz.x = s_p.x - s_m.x; Zz.y = s_p.y - s_m.y;
            Zz.z = s_p.z - s_m.z; Zz.w = s_p.w - s_m.w;

            float SzL = __shfl_up_sync(0xffffffffu, Sz.w, 1);
            float SzR = __shfl_down_sync(0xffffffffu, Sz.x, 1);
            float DzL = __shfl_up_sync(0xffffffffu, Dz.w, 1);
            float DzR = __shfl_down_sync(0xffffffffu, Dz.x, 1);
            float ZzL = __shfl_up_sync(0xffffffffu, Zz.w, 1);
            float ZzR = __shfl_down_sync(0xffffffffu, Zz.x, 1);
            if (lane == 0)  { SzL = 0.f; DzL = 0.f; ZzL = 0.f; }
            if (lane == 31) { SzR = 0.f; DzR = 0.f; ZzR = 0.f; }

            float4 vx, vy, vz;
            vx.x = Sz.y - SzL;  vx.y = Sz.z - Sz.x;
            vx.z = Sz.w - Sz.y; vx.w = SzR  - Sz.z;
            vy.x = DzL  + 2.f * Dz.x + Dz.y;
            vy.y = Dz.x + 2.f * Dz.y + Dz.z;
            vy.z = Dz.y + 2.f * Dz.z + Dz.w;
            vy.w = Dz.z + 2.f * Dz.w + DzR;
            vz.x = ZzL  + 2.f * Zz.x + Zz.y;
            vz.y = Zz.x + 2.f * Zz.y + Zz.z;
            vz.z = Zz.y + 2.f * Zz.z + Zz.w;
            vz.w = Zz.z + 2.f * Zz.w + ZzR;

            const int o = obase + (pz - 1) * HW_;
            __stcs(reinterpret_cast<float4*>(gx + o), vx);
            __stcs(reinterpret_cast<float4*>(gy + o), vy);
            __stcs(reinterpret_cast<float4*>(gz + o), vz);
        }
        s_m = s_0; s_0 = s_p;
        d_m = d_0; d_0 = d_p;
    }
}

extern "C" void kernel_launch(void* const* d_in, const int* in_sizes, int n_in,
                              void* d_out, int out_size) {
    const float* x = (const float*)d_in[0];
    float* out = (float*)d_out;

    dim3 block(32, YT_, 1);            // 256 threads
    dim3 grid(H_ / YT_, NC_, 1);       // 512 blocks, one wave
    sobel3d_kernel<<<grid, block>>>(x, out);
}